// round 16
// baseline (speedup 1.0000x reference)
#include <cuda_runtime.h>
#include <cuda_fp16.h>
#include <cstdint>

#define TT 8192
#define NH 2048
#define NF 512
#define NC 512
#define SEG 512
#define NSEG (TT / SEG)       // 16
#define NPROD 128             // producer blocks (64 unit-groups x 2 seg-halves)
#define NTILES 256            // 64 time-tiles x 4 class-tiles
#define WARMUP 4096

// ------------------------- scratch (static device globals) ------------------
__device__ __half g_H16[(long long)TT * NH];   // 32 MB: fp16 h, perm16 K
__device__ __half g_Vr16[(long long)NC * NH];  // fp16 V, perm16 K
__device__ float  g_Ut[(long long)NF * NH];    // U^T [feature][hidden]
__device__ int    g_ids[TT];
__device__ int    g_done[NSEG];
__device__ int    g_tile;
__device__ int    g_flag;                      // W != I
__device__ int    g_flag2;                     // guard tripped

// perm16 on fp16 elements: pair p=(i>>1)&7 -> (p<4 ? 2p : 2(p-4)+1); keeps
// (k,k+1) and (k+8,k+9) adjacent -> single LDS.64 fragments.
__host__ __device__ __forceinline__ int perm16(int i) {
    int p = (i >> 1) & 7, s = i & 1;
    int pp = (p < 4) ? (2 * p) : (2 * (p - 4) + 1);
    return (i & ~15) | (pp << 1) | s;
}

// ------------------------- PTX helpers --------------------------------------
__device__ __forceinline__ uint32_t smem_to_u32(const void* p) {
    uint32_t a;
    asm("{ .reg .u64 t; cvta.to.shared.u64 t, %1; cvt.u32.u64 %0, t; }"
        : "=r"(a) : "l"(p));
    return a;
}
#define CP_ASYNC16(dst, src) \
    asm volatile("cp.async.cg.shared.global [%0], [%1], 16;" :: "r"(dst), "l"(src) : "memory")
#define CP_COMMIT() asm volatile("cp.async.commit_group;" ::: "memory")

__device__ __forceinline__ void mma_f16_16816(float* d, const uint32_t* a,
                                              const uint32_t* b) {
    asm volatile(
        "mma.sync.aligned.m16n8k16.row.col.f32.f16.f16.f32 "
        "{%0,%1,%2,%3}, {%4,%5,%6,%7}, {%8,%9}, {%0,%1,%2,%3};"
        : "+f"(d[0]), "+f"(d[1]), "+f"(d[2]), "+f"(d[3])
        : "r"(a[0]), "r"(a[1]), "r"(a[2]), "r"(a[3]), "r"(b[0]), "r"(b[1]));
}

// ------------------------- merged prelude kernel ----------------------------
// block ranges: [0,8) init ids+flags | [8,1032) transposeU | [1032,5128) roundV
//               | [5128,5384) umax guard
#define PRE_INIT 8
#define PRE_TU   (PRE_INIT + 1024)
#define PRE_RV   (PRE_TU + 4096)
#define PRE_UM   (PRE_RV + 256)

__global__ void prelude_k(const int* __restrict__ ids32,
                          const float* __restrict__ U,
                          const float* __restrict__ V,
                          const float* __restrict__ h0) {
    int b = blockIdx.x;
    int tid = threadIdx.x;
    if (b < PRE_INIT) {
        __shared__ int mode;
        if (tid == 0) {
            if (b == 0) {
                g_flag = 0; g_flag2 = 0; g_tile = 0;
                for (int s = 0; s < NSEG; s++) g_done[s] = 0;
            }
            int allzero = 1;
#pragma unroll
            for (int j = 1; j < 64; j += 2)
                if (ids32[j] != 0) allzero = 0;
            mode = allzero;   // int64 input -> odd 32-bit words all zero
        }
        __syncthreads();
        for (int t = b * 256 + tid; t < TT; t += PRE_INIT * 256)
            g_ids[t] = mode ? ids32[2 * t] : ids32[t];
    } else if (b < PRE_TU) {
        __shared__ float tile[32][33];
        int tb = b - PRE_INIT;
        int bx = (tb & 15) * 32, by = (tb >> 4) * 32;
        int x = tid & 31, y = tid >> 5;   // 32x8
#pragma unroll
        for (int j = 0; j < 32; j += 8)
            tile[y + j][x] = U[(long long)(by + y + j) * NF + bx + x];
        __syncthreads();
#pragma unroll
        for (int j = 0; j < 32; j += 8)
            g_Ut[(long long)(bx + y + j) * NH + by + x] = tile[x][y + j];
    } else if (b < PRE_RV) {
        int idx = (b - PRE_TU) * 256 + tid;
        if (idx < NC * NH) {
            int c = idx >> 11, k = idx & (NH - 1);
            g_Vr16[(long long)c * NH + perm16(k)] = __float2half_rn(V[idx]);
        }
    } else {
        int i = (b - PRE_RV) * 8 + (tid >> 5);   // unit = row of U
        int lane = tid & 31;
        const float* row = U + (long long)i * NF;
        float um = 0.0f;
#pragma unroll
        for (int f = lane; f < NF; f += 32) um = fmaxf(um, fabsf(row[f]));
#pragma unroll
        for (int o = 16; o; o >>= 1)
            um = fmaxf(um, __shfl_xor_sync(0xFFFFFFFFu, um, o));
        if (lane == 0 && (um > 0.06f || fabsf(h0[i]) > 0.45f))
            atomicExch(&g_flag2, 1);
    }
}

// ------------------------- fused persistent kernel --------------------------
#define CHN 32                  // 64 k-halves per chunk (2048/64)
#define ROWB2 160               // smem row bytes (128 data + 32 pad)
#define TILE_B (128 * ROWB2)    // 20480
#define STAGE_B2 (2 * TILE_B)   // 40960
#define SMEM_TILEIDX (3 * STAGE_B2)
#define SMEM_FUSED (3 * STAGE_B2 + 64)   // 122944 B -> 1 block/SM

__global__ __launch_bounds__(256) void fused_k(const float* __restrict__ h0,
                                               const float* __restrict__ W,
                                               float* out_h,
                                               float* __restrict__ O,
                                               int nblk) {
    extern __shared__ float sdyn[];
    int tid = threadIdx.x;
    int lane = tid & 31, wid = tid >> 5;

    const float C3 = -0.33333333333f, C5 = 0.13333333333f;
    const float C7 = -0.05396825397f, C9 = 0.02186948853f;
    const float C11 = -0.00886323552f;

    if (blockIdx.x < NPROD) {
        // ====== producer block: 8 warps = 8 segments (2 per SMSP) ======
        float* su = sdyn;                            // [512][32]
        int* sidoff = (int*)(sdyn + NF * 32);        // TT+16 byte offsets
        int ug = blockIdx.x >> 1;                    // unit group 0..63
        int shalf = (blockIdx.x & 1) * 8;            // segments {0-7} or {8-15}

        const float* Us = g_Ut + ug * 32;
        for (int k = tid; k < NF * 8; k += 256) {
            int f = k >> 3, q = k & 7;
            float4 v = *reinterpret_cast<const float4*>(Us + (long long)f * NH + q * 4);
            *reinterpret_cast<float4*>(su + f * 32 + q * 4) = v;
        }
        for (int t = tid; t < TT; t += 256) sidoff[t] = g_ids[t] << 7;  // *128B
        if (tid < 16) sidoff[TT + tid] = 0;
        __syncthreads();

        {
            int s = shalf + wid;                     // this warp's segment
            int i = ug * 32 + lane;
            const char* sub = (const char*)su + lane * 4;
#define SU_AT(off) (*reinterpret_cast<const float*>(sub + (off)))
            int ts = s * SEG, te = ts + SEG;
            int t0 = ts - WARMUP; if (t0 < 0) t0 = 0;

            float x = ((t0 == 0) ? h0[i] : 0.0f) + SU_AT(sidoff[t0]);
            float u1 = SU_AT(sidoff[t0 + 1]);
            float u2 = SU_AT(sidoff[t0 + 2]);
            int o3 = sidoff[t0 + 3];
            float p = 1.0f;

#define POLY(UN, XN) do {                                                      \
            float x2 = x * x;                                                  \
            float x4 = x2 * x2;                                                \
            float A  = fmaf(x2, C3, 1.0f);                                     \
            float B  = fmaf(x2, C7, C5);                                       \
            float Cc = fmaf(x2, C11, C9);                                      \
            float D  = fmaf(x4, Cc, B);                                        \
            float xx4 = x * x4;                                                \
            (XN) = fmaf(xx4, D, fmaf(x, A, (UN)));                             \
        } while (0)

            // ---- warmup (no stores; contraction guard on 1-in-4 steps) ----
            for (int t = t0; t < ts; t += 4) {
                float xn;
                float u3 = SU_AT(o3); o3 = sidoff[t + 4];
                POLY(u1, xn);
                float hg = xn - u1;
                p *= fmaf(-hg, hg, 1.0f);
                x = xn; u1 = u2; u2 = u3;
                u3 = SU_AT(o3); o3 = sidoff[t + 5];
                POLY(u1, xn); x = xn; u1 = u2; u2 = u3;
                u3 = SU_AT(o3); o3 = sidoff[t + 6];
                POLY(u1, xn); x = xn; u1 = u2; u2 = u3;
                u3 = SU_AT(o3); o3 = sidoff[t + 7];
                POLY(u1, xn); x = xn; u1 = u2; u2 = u3;
            }
            if (t0 > 0 && p > 0.05f) atomicExch(&g_flag2, 1);

            // ---- segment (fp16 stores, perm16 column) ----
            float hlast = 0.0f;
            __half* hp = g_H16 + (long long)ts * NH + perm16(i);
#pragma unroll 4
            for (int t = ts; t < te; ++t) {
                float xn;
                float u3 = SU_AT(o3); o3 = sidoff[t + 4];
                POLY(u1, xn);
                float h = xn - u1;                   // h_t, off-chain
                *hp = __float2half_rn(h);
                hp += NH;
                hlast = h;
                x = xn; u1 = u2; u2 = u3;
            }
            if (s == NSEG - 1 && out_h) out_h[i] = hlast;
            __threadfence();
            __syncwarp();
            if (lane == 0) atomicAdd(&g_done[s], 1);
#undef SU_AT
#undef POLY
        }
        asm volatile("bar.sync 4, 256;" ::: "memory");
    } else {
        // ============ dedicated consumer: W==I check during warmup ==========
        int nded = nblk - NPROD;
        long long total = (long long)NH * NH;
        long long stride = (long long)nded * 256;
        int bad = 0;
        for (long long idx = (long long)(blockIdx.x - NPROD) * 256 + tid;
             idx < total; idx += stride) {
            int r = (int)(idx >> 11), cc = (int)(idx & (NH - 1));
            bad |= (W[idx] != ((r == cc) ? 1.0f : 0.0f));
        }
        if (__syncthreads_or(bad)) { if (tid == 0) atomicExch(&g_flag, 1); }
    }

    // =================== fp16 GEMM worker loop ==============================
    char* smc = (char*)sdyn;
    uint32_t sb = smem_to_u32(sdyn);
    int* tile_sh = (int*)(smc + SMEM_TILEIDX);
    int wm = (wid & 3) * 32, wn = (wid >> 2) * 64;
    int lq = lane >> 2, lr = lane & 3;

    for (;;) {
        if (tid == 0) *tile_sh = atomicAdd(&g_tile, 1);
        __syncthreads();
        int tau = *tile_sh;
        __syncthreads();
        if (tau >= NTILES) break;

        int bt = (tau >> 2) * 128;       // time tile (ascending)
        int bc = (tau & 3) * 128;        // class tile
        if (tid == 0) {
            const volatile int* vd = g_done;
            int s = tau >> 4;            // 512-row segment of this tile
            while (vd[s] < 64) __nanosleep(256);
        }
        __syncthreads();
        __threadfence();                 // acquire

        const __half* Ah = g_H16 + (long long)bt * NH;
        const __half* Bh = g_Vr16 + (long long)bc * NH;

        float d[2][8][4];
#pragma unroll
        for (int mi = 0; mi < 2; mi++)
#pragma unroll
            for (int ni = 0; ni < 8; ni++)
#pragma unroll
                for (int q = 0; q < 4; q++) d[mi][ni][q] = 0.0f;

#define LOAD_STAGE(c, stg) do {                                                \
        uint32_t ab = sb + (uint32_t)(stg) * STAGE_B2;                         \
        uint32_t bbf = ab + TILE_B;                                            \
        int k0 = (c) * 64;                                                     \
        _Pragma("unroll")                                                      \
        for (int j = 0; j < 4; j++) {                                          \
            int chunk = tid + 256 * j;                                         \
            int row = chunk >> 3, seg = chunk & 7;                             \
            uint32_t off = (uint32_t)(row * ROWB2 + seg * 16);                 \
            CP_ASYNC16(ab + off, Ah + (long long)row * NH + k0 + seg * 8);     \
            CP_ASYNC16(bbf + off, Bh + (long long)row * NH + k0 + seg * 8);    \
        }                                                                      \
        CP_COMMIT();                                                           \
    } while (0)

        LOAD_STAGE(0, 0);
        LOAD_STAGE(1, 1);

        for (int c = 0; c < CHN; c++) {
            if (c < CHN - 1) asm volatile("cp.async.wait_group 1;" ::: "memory");
            else             asm volatile("cp.async.wait_group 0;" ::: "memory");
            __syncthreads();
            if (c + 2 < CHN) LOAD_STAGE(c + 2, (c + 2) % 3);

            const char* As = smc + (c % 3) * STAGE_B2;
            const char* Bs = As + TILE_B;
#pragma unroll
            for (int kk = 0; kk < 4; kk++) {
                int kb = kk * 32 + lr * 8;           // byte offset in row
                uint32_t a[2][4];
#pragma unroll
                for (int mi = 0; mi < 2; mi++) {
                    uint2 pa = *reinterpret_cast<const uint2*>(
                        As + (wm + mi * 16 + lq) * ROWB2 + kb);
                    uint2 qa = *reinterpret_cast<const uint2*>(
                        As + (wm + mi * 16 + 8 + lq) * ROWB2 + kb);
                    a[mi][0] = pa.x;
                    a[mi][1] = qa.x;
                    a[mi][2] = pa.y;
                    a[mi][3] = qa.y;
                }
                uint32_t b[8][2];
#pragma unroll
                for (int ni = 0; ni < 8; ni++) {
                    uint2 pb = *reinterpret_cast<const uint2*>(
                        Bs + (wn + ni * 8 + lq) * ROWB2 + kb);
                    b[ni][0] = pb.x;
                    b[ni][1] = pb.y;
                }
#pragma unroll
                for (int mi = 0; mi < 2; mi++)
#pragma unroll
                    for (int ni = 0; ni < 8; ni++)
                        mma_f16_16816(d[mi][ni], a[mi], b[ni]);
            }
        }

#pragma unroll
        for (int mi = 0; mi < 2; mi++) {
            int row0 = bt + wm + mi * 16 + lq;
#pragma unroll
            for (int ni = 0; ni < 8; ni++) {
                int col = bc + wn + ni * 8 + lr * 2;
                float2 v01 = make_float2(d[mi][ni][0], d[mi][ni][1]);
                float2 v23 = make_float2(d[mi][ni][2], d[mi][ni][3]);
                *reinterpret_cast<float2*>(O + (long long)row0 * NC + col) = v01;
                *reinterpret_cast<float2*>(O + (long long)(row0 + 8) * NC + col) = v23;
            }
        }
        __syncthreads();
    }
}

// Precise sequential re-run (only if guard tripped).
__global__ void recur_seq_k(const float* __restrict__ h0, float* out_h) {
    if (g_flag2 == 0) return;
    int i = blockIdx.x * 32 + threadIdx.x;
    const float* Ucol = g_Ut + i;
    float h = h0[i];
    for (int t = 0; t < TT; ++t) {
        h = tanhf(h + Ucol[(long long)g_ids[t] * NH]);
        g_H16[(long long)t * NH + perm16(i)] = __float2half_rn(h);
    }
    if (out_h) out_h[i] = h;
}

// GEMM redo (only if guard tripped). Both operands perm16-consistent.
__global__ void gemm_fix_k(float* __restrict__ O) {
    if (g_flag2 == 0) return;
    for (int t = blockIdx.x; t < TT; t += gridDim.x) {
        const __half* hrow = g_H16 + (long long)t * NH;
        for (int c = threadIdx.x; c < NC; c += blockDim.x) {
            const __half* vrow = g_Vr16 + (long long)c * NH;
            float acc = 0.0f;
            for (int k = 0; k < NH; ++k)
                acc = fmaf(__half2float(hrow[k]), __half2float(vrow[k]), acc);
            O[(long long)t * NC + c] = acc;
        }
    }
}

// ------------------------- generic fallback (W != I) ------------------------
__global__ void fallback_k(const float* __restrict__ h0,
                           const float* __restrict__ W,
                           const float* __restrict__ U,
                           const float* __restrict__ V,
                           float* out_h, float* __restrict__ out_o) {
    if (g_flag == 0) return;
    __shared__ float h[NH];
    __shared__ float xn[NH];
    int tid = threadIdx.x;
    for (int i = tid; i < NH; i += blockDim.x) h[i] = h0[i];
    __syncthreads();
    for (int t = 0; t < TT; ++t) {
        int id = g_ids[t];
        for (int r0 = tid; r0 < NH; r0 += blockDim.x) {
            float acc = U[(long long)r0 * NF + id];
            const float* wr = W + (long long)r0 * NH;
            for (int k = 0; k < NH; ++k) acc = fmaf(wr[k], h[k], acc);
            xn[r0] = tanhf(acc);
        }
        __syncthreads();
        for (int i = tid; i < NH; i += blockDim.x) h[i] = xn[i];
        __syncthreads();
        for (int c = tid; c < NC; c += blockDim.x) {
            float acc = 0.0f;
            const float* vr = V + (long long)c * NH;
            for (int k = 0; k < NH; ++k) acc = fmaf(vr[k], h[k], acc);
            out_o[(long long)t * NC + c] = acc;
        }
        __syncthreads();
    }
    if (out_h)
        for (int i = tid; i < NH; i += blockDim.x) out_h[i] = h[i];
}

// ---------------------------------------------------------------------------
extern "C" void kernel_launch(void* const* d_in, const int* in_sizes, int n_in,
                              void* d_out, int out_size) {
    const float* h0    = (const float*)d_in[0];
    const int*   ids32 = (const int*)d_in[1];
    const float* W     = (const float*)d_in[2];
    const float* U     = (const float*)d_in[3];
    const float* V     = (const float*)d_in[4];
    float* out = (float*)d_out;

    float* out_h;
    float* out_o;
    if (out_size == NH + TT * NC) { out_h = out; out_o = out + NH; }
    else                          { out_h = nullptr; out_o = out; }

    int nsm = 148;
    cudaDeviceGetAttribute(&nsm, cudaDevAttrMultiProcessorCount, 0);
    int nblk = nsm;
    if (nblk < NPROD + 1) nblk = NPROD + 1;

    cudaFuncSetAttribute(fused_k, cudaFuncAttributeMaxDynamicSharedMemorySize,
                         SMEM_FUSED);

    prelude_k<<<PRE_UM, 256>>>(ids32, U, V, h0);
    fused_k<<<nblk, 256, SMEM_FUSED>>>(h0, W, out_h, out_o, nblk);
    recur_seq_k<<<NH / 32, 32>>>(h0, out_h);    // no-op unless guard tripped
    gemm_fix_k<<<256, 256>>>(out_o);            // no-op unless guard tripped
    fallback_k<<<1, 1024>>>(h0, W, U, V, out_h, out_o);
    (void)in_sizes; (void)n_in;
}

// round 17
// speedup vs baseline: 1.0714x; 1.0714x over previous
#include <cuda_runtime.h>
#include <cuda_fp16.h>
#include <cstdint>

#define TT 8192
#define NH 2048
#define NF 512
#define NC 512
#define SEG 1024
#define NSEG (TT / SEG)       // 8
#define NPROD 128             // producer blocks (64 unit-groups x 2 seg-halves)
#define NTILES 256            // 64 time-tiles x 4 class-tiles
#define WARMUP 4096

// ------------------------- scratch (static device globals) ------------------
__device__ __half g_H16[(long long)TT * NH];   // 32 MB: fp16 h, perm16 K
__device__ __half g_Vr16[(long long)NC * NH];  // fp16 V, perm16 K
__device__ float  g_Ut[(long long)NF * NH];    // U^T [feature][hidden]
__device__ int    g_ids[TT];
__device__ int    g_done[NSEG];
__device__ int    g_tile;
__device__ int    g_flag;                      // W != I
__device__ int    g_flag2;                     // guard tripped

// perm16 on fp16 elements: pair p=(i>>1)&7 -> (p<4 ? 2p : 2(p-4)+1); keeps
// (k,k+1) and (k+8,k+9) adjacent -> single LDS.64 fragments.
__host__ __device__ __forceinline__ int perm16(int i) {
    int p = (i >> 1) & 7, s = i & 1;
    int pp = (p < 4) ? (2 * p) : (2 * (p - 4) + 1);
    return (i & ~15) | (pp << 1) | s;
}

// ------------------------- PTX helpers --------------------------------------
__device__ __forceinline__ uint32_t smem_to_u32(const void* p) {
    uint32_t a;
    asm("{ .reg .u64 t; cvta.to.shared.u64 t, %1; cvt.u32.u64 %0, t; }"
        : "=r"(a) : "l"(p));
    return a;
}
#define CP_ASYNC16(dst, src) \
    asm volatile("cp.async.cg.shared.global [%0], [%1], 16;" :: "r"(dst), "l"(src) : "memory")
#define CP_COMMIT() asm volatile("cp.async.commit_group;" ::: "memory")

__device__ __forceinline__ void mma_f16_16816(float* d, const uint32_t* a,
                                              const uint32_t* b) {
    asm volatile(
        "mma.sync.aligned.m16n8k16.row.col.f32.f16.f16.f32 "
        "{%0,%1,%2,%3}, {%4,%5,%6,%7}, {%8,%9}, {%0,%1,%2,%3};"
        : "+f"(d[0]), "+f"(d[1]), "+f"(d[2]), "+f"(d[3])
        : "r"(a[0]), "r"(a[1]), "r"(a[2]), "r"(a[3]), "r"(b[0]), "r"(b[1]));
}

// ------------------------- merged prelude kernel ----------------------------
// block ranges: [0,8) init ids+flags | [8,1032) transposeU | [1032,5128) roundV
//               | [5128,5384) umax guard
#define PRE_INIT 8
#define PRE_TU   (PRE_INIT + 1024)
#define PRE_RV   (PRE_TU + 4096)
#define PRE_UM   (PRE_RV + 256)

__global__ void prelude_k(const int* __restrict__ ids32,
                          const float* __restrict__ U,
                          const float* __restrict__ V,
                          const float* __restrict__ h0) {
    int b = blockIdx.x;
    int tid = threadIdx.x;
    if (b < PRE_INIT) {
        __shared__ int mode;
        if (tid == 0) {
            if (b == 0) {
                g_flag = 0; g_flag2 = 0; g_tile = 0;
                for (int s = 0; s < NSEG; s++) g_done[s] = 0;
            }
            int allzero = 1;
#pragma unroll
            for (int j = 1; j < 64; j += 2)
                if (ids32[j] != 0) allzero = 0;
            mode = allzero;   // int64 input -> odd 32-bit words all zero
        }
        __syncthreads();
        for (int t = b * 256 + tid; t < TT; t += PRE_INIT * 256)
            g_ids[t] = mode ? ids32[2 * t] : ids32[t];
    } else if (b < PRE_TU) {
        __shared__ float tile[32][33];
        int tb = b - PRE_INIT;
        int bx = (tb & 15) * 32, by = (tb >> 4) * 32;
        int x = tid & 31, y = tid >> 5;   // 32x8
#pragma unroll
        for (int j = 0; j < 32; j += 8)
            tile[y + j][x] = U[(long long)(by + y + j) * NF + bx + x];
        __syncthreads();
#pragma unroll
        for (int j = 0; j < 32; j += 8)
            g_Ut[(long long)(bx + y + j) * NH + by + x] = tile[x][y + j];
    } else if (b < PRE_RV) {
        int idx = (b - PRE_TU) * 256 + tid;
        if (idx < NC * NH) {
            int c = idx >> 11, k = idx & (NH - 1);
            g_Vr16[(long long)c * NH + perm16(k)] = __float2half_rn(V[idx]);
        }
    } else {
        int i = (b - PRE_RV) * 8 + (tid >> 5);   // unit = row of U
        int lane = tid & 31;
        const float* row = U + (long long)i * NF;
        float um = 0.0f;
#pragma unroll
        for (int f = lane; f < NF; f += 32) um = fmaxf(um, fabsf(row[f]));
#pragma unroll
        for (int o = 16; o; o >>= 1)
            um = fmaxf(um, __shfl_xor_sync(0xFFFFFFFFu, um, o));
        if (lane == 0 && (um > 0.06f || fabsf(h0[i]) > 0.45f))
            atomicExch(&g_flag2, 1);
    }
}

// ------------------------- fused persistent kernel --------------------------
#define CHN 32                  // 64 k-halves per chunk (2048/64)
#define ROWB2 160               // smem row bytes (128 data + 32 pad)
#define TILE_B (128 * ROWB2)    // 20480
#define STAGE_B2 (2 * TILE_B)   // 40960
#define SMEM_TILEIDX (3 * STAGE_B2)
#define SMEM_FUSED (3 * STAGE_B2 + 64)   // 122944 B -> 1 block/SM

__global__ __launch_bounds__(256) void fused_k(const float* __restrict__ h0,
                                               const float* __restrict__ W,
                                               float* out_h,
                                               float* __restrict__ O,
                                               int nblk) {
    extern __shared__ float sdyn[];
    int tid = threadIdx.x;
    int lane = tid & 31, wid = tid >> 5;

    const float C3 = -0.33333333333f, C5 = 0.13333333333f;
    const float C7 = -0.05396825397f, C9 = 0.02186948853f;
    const float C11 = -0.00886323552f;

    if (blockIdx.x < NPROD) {
        // ====== producer block: warps 0-3 (one per SMSP) = 4 segments ======
        float* su = sdyn;                            // [512][32]
        int* sidoff = (int*)(sdyn + NF * 32);        // TT+16 byte offsets
        int ug = blockIdx.x >> 1;                    // unit group 0..63
        int shalf = (blockIdx.x & 1) * 4;            // segments {0-3} or {4-7}

        const float* Us = g_Ut + ug * 32;
        for (int k = tid; k < NF * 8; k += 256) {
            int f = k >> 3, q = k & 7;
            float4 v = *reinterpret_cast<const float4*>(Us + (long long)f * NH + q * 4);
            *reinterpret_cast<float4*>(su + f * 32 + q * 4) = v;
        }
        for (int t = tid; t < TT; t += 256) sidoff[t] = g_ids[t] << 7;  // *128B
        if (tid < 16) sidoff[TT + tid] = 0;
        __syncthreads();

        if (wid < 4) {
            int s = shalf + wid;                     // this warp's segment
            int i = ug * 32 + lane;
            const char* sub = (const char*)su + lane * 4;
#define SU_AT(off) (*reinterpret_cast<const float*>(sub + (off)))
            int ts = s * SEG, te = ts + SEG;
            int t0 = ts - WARMUP; if (t0 < 0) t0 = 0;

            float x = ((t0 == 0) ? h0[i] : 0.0f) + SU_AT(sidoff[t0]);
            float u1 = SU_AT(sidoff[t0 + 1]);
            float u2 = SU_AT(sidoff[t0 + 2]);
            int o3 = sidoff[t0 + 3];
            float p = 1.0f;

#define POLY(UN, XN) do {                                                      \
            float x2 = x * x;                                                  \
            float x4 = x2 * x2;                                                \
            float A  = fmaf(x2, C3, 1.0f);                                     \
            float B  = fmaf(x2, C7, C5);                                       \
            float Cc = fmaf(x2, C11, C9);                                      \
            float D  = fmaf(x4, Cc, B);                                        \
            float xx4 = x * x4;                                                \
            (XN) = fmaf(xx4, D, fmaf(x, A, (UN)));                             \
        } while (0)

            // ---- warmup (no stores; contraction guard on 1-in-4 steps) ----
            for (int t = t0; t < ts; t += 4) {
                float xn;
                float u3 = SU_AT(o3); o3 = sidoff[t + 4];
                POLY(u1, xn);
                float hg = xn - u1;
                p *= fmaf(-hg, hg, 1.0f);
                x = xn; u1 = u2; u2 = u3;
                u3 = SU_AT(o3); o3 = sidoff[t + 5];
                POLY(u1, xn); x = xn; u1 = u2; u2 = u3;
                u3 = SU_AT(o3); o3 = sidoff[t + 6];
                POLY(u1, xn); x = xn; u1 = u2; u2 = u3;
                u3 = SU_AT(o3); o3 = sidoff[t + 7];
                POLY(u1, xn); x = xn; u1 = u2; u2 = u3;
            }
            if (t0 > 0 && p > 0.05f) atomicExch(&g_flag2, 1);

            // ---- segment (fp16 stores, perm16 column) ----
            float hlast = 0.0f;
            __half* hp = g_H16 + (long long)ts * NH + perm16(i);
#pragma unroll 4
            for (int t = ts; t < te; ++t) {
                float xn;
                float u3 = SU_AT(o3); o3 = sidoff[t + 4];
                POLY(u1, xn);
                float h = xn - u1;                   // h_t, off-chain
                *hp = __float2half_rn(h);
                hp += NH;
                hlast = h;
                x = xn; u1 = u2; u2 = u3;
            }
            if (s == NSEG - 1 && out_h) out_h[i] = hlast;
            __threadfence();
            __syncwarp();
            if (lane == 0) atomicAdd(&g_done[s], 1);
#undef SU_AT
#undef POLY
        }
        asm volatile("bar.sync 4, 256;" ::: "memory");
    } else {
        // ============ dedicated consumer: W==I check during warmup ==========
        int nded = nblk - NPROD;
        long long total = (long long)NH * NH;
        long long stride = (long long)nded * 256;
        int bad = 0;
        for (long long idx = (long long)(blockIdx.x - NPROD) * 256 + tid;
             idx < total; idx += stride) {
            int r = (int)(idx >> 11), cc = (int)(idx & (NH - 1));
            bad |= (W[idx] != ((r == cc) ? 1.0f : 0.0f));
        }
        if (__syncthreads_or(bad)) { if (tid == 0) atomicExch(&g_flag, 1); }
    }

    // =================== fp16 GEMM worker loop ==============================
    char* smc = (char*)sdyn;
    uint32_t sb = smem_to_u32(sdyn);
    int* tile_sh = (int*)(smc + SMEM_TILEIDX);
    int wm = (wid & 3) * 32, wn = (wid >> 2) * 64;
    int lq = lane >> 2, lr = lane & 3;

    for (;;) {
        if (tid == 0) *tile_sh = atomicAdd(&g_tile, 1);
        __syncthreads();
        int tau = *tile_sh;
        __syncthreads();
        if (tau >= NTILES) break;

        int bt = (tau >> 2) * 128;       // time tile (ascending)
        int bc = (tau & 3) * 128;        // class tile
        if (tid == 0) {
            const volatile int* vd = g_done;
            int s = tau >> 5;            // segment of this tile (8 segs)
            while (vd[s] < 64) __nanosleep(256);
        }
        __syncthreads();
        __threadfence();                 // acquire

        const __half* Ah = g_H16 + (long long)bt * NH;
        const __half* Bh = g_Vr16 + (long long)bc * NH;

        float d[2][8][4];
#pragma unroll
        for (int mi = 0; mi < 2; mi++)
#pragma unroll
            for (int ni = 0; ni < 8; ni++)
#pragma unroll
                for (int q = 0; q < 4; q++) d[mi][ni][q] = 0.0f;

#define LOAD_STAGE(c, stg) do {                                                \
        uint32_t ab = sb + (uint32_t)(stg) * STAGE_B2;                         \
        uint32_t bbf = ab + TILE_B;                                            \
        int k0 = (c) * 64;                                                     \
        _Pragma("unroll")                                                      \
        for (int j = 0; j < 4; j++) {                                          \
            int chunk = tid + 256 * j;                                         \
            int row = chunk >> 3, seg = chunk & 7;                             \
            uint32_t off = (uint32_t)(row * ROWB2 + seg * 16);                 \
            CP_ASYNC16(ab + off, Ah + (long long)row * NH + k0 + seg * 8);     \
            CP_ASYNC16(bbf + off, Bh + (long long)row * NH + k0 + seg * 8);    \
        }                                                                      \
        CP_COMMIT();                                                           \
    } while (0)

        LOAD_STAGE(0, 0);
        LOAD_STAGE(1, 1);

        for (int c = 0; c < CHN; c++) {
            if (c < CHN - 1) asm volatile("cp.async.wait_group 1;" ::: "memory");
            else             asm volatile("cp.async.wait_group 0;" ::: "memory");
            __syncthreads();
            if (c + 2 < CHN) LOAD_STAGE(c + 2, (c + 2) % 3);

            const char* As = smc + (c % 3) * STAGE_B2;
            const char* Bs = As + TILE_B;
#pragma unroll
            for (int kk = 0; kk < 4; kk++) {
                int kb = kk * 32 + lr * 8;           // byte offset in row
                uint32_t a[2][4];
#pragma unroll
                for (int mi = 0; mi < 2; mi++) {
                    uint2 pa = *reinterpret_cast<const uint2*>(
                        As + (wm + mi * 16 + lq) * ROWB2 + kb);
                    uint2 qa = *reinterpret_cast<const uint2*>(
                        As + (wm + mi * 16 + 8 + lq) * ROWB2 + kb);
                    a[mi][0] = pa.x;
                    a[mi][1] = qa.x;
                    a[mi][2] = pa.y;
                    a[mi][3] = qa.y;
                }
                uint32_t b[8][2];
#pragma unroll
                for (int ni = 0; ni < 8; ni++) {
                    uint2 pb = *reinterpret_cast<const uint2*>(
                        Bs + (wn + ni * 8 + lq) * ROWB2 + kb);
                    b[ni][0] = pb.x;
                    b[ni][1] = pb.y;
                }
#pragma unroll
                for (int mi = 0; mi < 2; mi++)
#pragma unroll
                    for (int ni = 0; ni < 8; ni++)
                        mma_f16_16816(d[mi][ni], a[mi], b[ni]);
            }
        }

#pragma unroll
        for (int mi = 0; mi < 2; mi++) {
            int row0 = bt + wm + mi * 16 + lq;
#pragma unroll
            for (int ni = 0; ni < 8; ni++) {
                int col = bc + wn + ni * 8 + lr * 2;
                float2 v01 = make_float2(d[mi][ni][0], d[mi][ni][1]);
                float2 v23 = make_float2(d[mi][ni][2], d[mi][ni][3]);
                *reinterpret_cast<float2*>(O + (long long)row0 * NC + col) = v01;
                *reinterpret_cast<float2*>(O + (long long)(row0 + 8) * NC + col) = v23;
            }
        }
        __syncthreads();
    }
}

// Precise sequential re-run (only if guard tripped).
__global__ void recur_seq_k(const float* __restrict__ h0, float* out_h) {
    if (g_flag2 == 0) return;
    int i = blockIdx.x * 32 + threadIdx.x;
    const float* Ucol = g_Ut + i;
    float h = h0[i];
    for (int t = 0; t < TT; ++t) {
        h = tanhf(h + Ucol[(long long)g_ids[t] * NH]);
        g_H16[(long long)t * NH + perm16(i)] = __float2half_rn(h);
    }
    if (out_h) out_h[i] = h;
}

// GEMM redo (only if guard tripped). Both operands perm16-consistent.
__global__ void gemm_fix_k(float* __restrict__ O) {
    if (g_flag2 == 0) return;
    for (int t = blockIdx.x; t < TT; t += gridDim.x) {
        const __half* hrow = g_H16 + (long long)t * NH;
        for (int c = threadIdx.x; c < NC; c += blockDim.x) {
            const __half* vrow = g_Vr16 + (long long)c * NH;
            float acc = 0.0f;
            for (int k = 0; k < NH; ++k)
                acc = fmaf(__half2float(hrow[k]), __half2float(vrow[k]), acc);
            O[(long long)t * NC + c] = acc;
        }
    }
}

// ------------------------- generic fallback (W != I) ------------------------
__global__ void fallback_k(const float* __restrict__ h0,
                           const float* __restrict__ W,
                           const float* __restrict__ U,
                           const float* __restrict__ V,
                           float* out_h, float* __restrict__ out_o) {
    if (g_flag == 0) return;
    __shared__ float h[NH];
    __shared__ float xn[NH];
    int tid = threadIdx.x;
    for (int i = tid; i < NH; i += blockDim.x) h[i] = h0[i];
    __syncthreads();
    for (int t = 0; t < TT; ++t) {
        int id = g_ids[t];
        for (int r0 = tid; r0 < NH; r0 += blockDim.x) {
            float acc = U[(long long)r0 * NF + id];
            const float* wr = W + (long long)r0 * NH;
            for (int k = 0; k < NH; ++k) acc = fmaf(wr[k], h[k], acc);
            xn[r0] = tanhf(acc);
        }
        __syncthreads();
        for (int i = tid; i < NH; i += blockDim.x) h[i] = xn[i];
        __syncthreads();
        for (int c = tid; c < NC; c += blockDim.x) {
            float acc = 0.0f;
            const float* vr = V + (long long)c * NH;
            for (int k = 0; k < NH; ++k) acc = fmaf(vr[k], h[k], acc);
            out_o[(long long)t * NC + c] = acc;
        }
        __syncthreads();
    }
    if (out_h)
        for (int i = tid; i < NH; i += blockDim.x) out_h[i] = h[i];
}

// ---------------------------------------------------------------------------
extern "C" void kernel_launch(void* const* d_in, const int* in_sizes, int n_in,
                              void* d_out, int out_size) {
    const float* h0    = (const float*)d_in[0];
    const int*   ids32 = (const int*)d_in[1];
    const float* W     = (const float*)d_in[2];
    const float* U     = (const float*)d_in[3];
    const float* V     = (const float*)d_in[4];
    float* out = (float*)d_out;

    float* out_h;
    float* out_o;
    if (out_size == NH + TT * NC) { out_h = out; out_o = out + NH; }
    else                          { out_h = nullptr; out_o = out; }

    int nsm = 148;
    cudaDeviceGetAttribute(&nsm, cudaDevAttrMultiProcessorCount, 0);
    int nblk = nsm;
    if (nblk < NPROD + 1) nblk = NPROD + 1;

    cudaFuncSetAttribute(fused_k, cudaFuncAttributeMaxDynamicSharedMemorySize,
                         SMEM_FUSED);

    prelude_k<<<PRE_UM, 256>>>(ids32, U, V, h0);
    fused_k<<<nblk, 256, SMEM_FUSED>>>(h0, W, out_h, out_o, nblk);
    recur_seq_k<<<NH / 32, 32>>>(h0, out_h);    // no-op unless guard tripped
    gemm_fix_k<<<256, 256>>>(out_o);            // no-op unless guard tripped
    fallback_k<<<1, 1024>>>(h0, W, U, V, out_h, out_o);
    (void)in_sizes; (void)n_in;
}